// round 2
// baseline (speedup 1.0000x reference)
#include <cuda_runtime.h>
#include <cstdint>

#define BN   2048      // batch rows
#define NL   64        // latent dim
#define NU   16        // nuisance dim
#define NO   2048      // output dim
#define TM   16        // rows per block tile (all same nuisance id)
#define NT   512       // threads per block: thread t owns float4 column t (4*t .. 4*t+3)
#define MAXTILES (BN / TM)   // 128 (covers worst case: one id owns all rows)

// Scratch (device globals — no allocation allowed). Recomputed every launch.
__device__ int g_ids[BN];
__device__ int g_row_order[BN];
__device__ int g_group_start[NU + 1];

// ---------- packed f32x2 helpers (Blackwell FFMA2 path, PTX-only) ----------
__device__ __forceinline__ unsigned long long pack2(float x, float y) {
    unsigned long long r;
    asm("mov.b64 %0, {%1, %2};" : "=l"(r) : "f"(x), "f"(y));
    return r;
}
__device__ __forceinline__ void unpack2(unsigned long long v, float& x, float& y) {
    asm("mov.b64 {%0, %1}, %2;" : "=f"(x), "=f"(y) : "l"(v));
}
__device__ __forceinline__ void fma2(unsigned long long& d,
                                     unsigned long long a,
                                     unsigned long long b) {
    asm("fma.rn.f32x2 %0, %1, %2, %0;" : "+l"(d) : "l"(a), "l"(b));
}

__device__ __forceinline__ float warpMax(float v) {
    #pragma unroll
    for (int o = 16; o > 0; o >>= 1) v = fmaxf(v, __shfl_xor_sync(0xFFFFFFFFu, v, o));
    return v;
}
__device__ __forceinline__ float warpSum(float v) {
    #pragma unroll
    for (int o = 16; o > 0; o >>= 1) v += __shfl_xor_sync(0xFFFFFFFFu, v, o);
    return v;
}

// ---------- kernel 1: per-row argmax id + counting sort into id groups ----------
__global__ void sort_kernel(const float* __restrict__ z) {
    __shared__ int hist[NU];
    __shared__ int cursor[NU];
    int tid = threadIdx.x;
    if (tid < NU) hist[tid] = 0;
    __syncthreads();

    for (int b = tid; b < BN; b += blockDim.x) {
        const float* zn = z + (size_t)b * (NL + NU) + NL;
        int best = 0;
        float bv = zn[0];
        #pragma unroll
        for (int j = 1; j < NU; j++) {
            float v = zn[j];
            if (v > bv) { bv = v; best = j; }   // first-max wins, matches jnp.argmax
        }
        g_ids[b] = best;
        atomicAdd(&hist[best], 1);
    }
    __syncthreads();

    if (tid == 0) {
        int acc = 0;
        #pragma unroll
        for (int i = 0; i < NU; i++) {
            g_group_start[i] = acc;
            cursor[i] = acc;
            acc += hist[i];
        }
        g_group_start[NU] = acc;   // == BN
    }
    __syncthreads();

    for (int b = tid; b < BN; b += blockDim.x) {
        int id = g_ids[b];
        int p = atomicAdd(&cursor[id], 1);
        g_row_order[p] = b;
    }
}

// ---------- kernel 2: grouped fused decoder ----------
// grid = (NU, MAXTILES). Block (id, tile) handles TM rows of group `id`;
// thread t owns output columns [4t, 4t+4). Two rows packed per f32x2 accumulator.
__global__ __launch_bounds__(NT, 1)
void decoder_kernel(const float* __restrict__ z,
                    const float* __restrict__ size_factor,
                    const float* __restrict__ amat_w,
                    const float* __restrict__ amat_site,
                    const float* __restrict__ offsets,
                    float* __restrict__ out) {
    const int id   = blockIdx.x;
    const int tile = blockIdx.y;
    const int gs = g_group_start[id];
    const int ge = g_group_start[id + 1];
    const int row_base = gs + tile * TM;
    if (row_base >= ge) return;
    const int nrows = min(TM, ge - row_base);

    __shared__ float z2[NL * TM];        // z2[(l*(TM/2)+rp)*2 + h] = z[row 2rp+h][l]
    __shared__ float sf_s[TM];
    __shared__ int   rows_s[TM];
    __shared__ float wred[TM * 16];
    __shared__ float rowmax_s[TM];
    __shared__ float rowsum_s[TM];

    const int tid = threadIdx.x;
    const int wid = tid >> 5;
    const int col = tid * 4;

    if (tid < TM) {
        int row = (tid < nrows) ? g_row_order[row_base + tid] : -1;
        rows_s[tid] = row;
        sf_s[tid] = (row >= 0) ? size_factor[row] : 1.0f;
    }
    __syncthreads();

    // Stage z, transposed and pre-paired for f32x2 broadcasts.
    for (int i = tid; i < TM * NL; i += NT) {
        int r = i / NL, l = i % NL;
        int row = rows_s[r];
        float v = (row >= 0) ? z[(size_t)row * (NL + NU) + l] : 0.0f;
        z2[(l * (TM / 2) + (r >> 1)) * 2 + (r & 1)] = v;
    }
    __syncthreads();

    const float* As = amat_site + (size_t)id * NL * NO;
    const unsigned long long* z2u = (const unsigned long long*)z2;

    unsigned long long acc[TM / 2][4];
    #pragma unroll
    for (int rp = 0; rp < TM / 2; rp++)
        #pragma unroll
        for (int j = 0; j < 4; j++) acc[rp][j] = 0ull;

    #pragma unroll 2
    for (int l = 0; l < NL; l++) {
        const float4 w4 = *(const float4*)(amat_w + (size_t)l * NO + col);
        const float4 s4 = *(const float4*)(As     + (size_t)l * NO + col);
        unsigned long long cd0 = pack2(w4.x + s4.x, w4.x + s4.x);
        unsigned long long cd1 = pack2(w4.y + s4.y, w4.y + s4.y);
        unsigned long long cd2 = pack2(w4.z + s4.z, w4.z + s4.z);
        unsigned long long cd3 = pack2(w4.w + s4.w, w4.w + s4.w);
        const unsigned long long* zrow = z2u + l * (TM / 2);
        #pragma unroll
        for (int rp = 0; rp < TM / 2; rp++) {
            unsigned long long zp = zrow[rp];   // (z[2rp][l], z[2rp+1][l]) broadcast LDS.64
            fma2(acc[rp][0], cd0, zp);
            fma2(acc[rp][1], cd1, zp);
            fma2(acc[rp][2], cd2, zp);
            fma2(acc[rp][3], cd3, zp);
        }
    }

    // Unpack logits, add offsets row.
    float lv[TM][4];
    #pragma unroll
    for (int rp = 0; rp < TM / 2; rp++)
        #pragma unroll
        for (int j = 0; j < 4; j++) {
            float a, b;
            unpack2(acc[rp][j], a, b);
            lv[2 * rp][j] = a;
            lv[2 * rp + 1][j] = b;
        }
    const float4 off4 = *(const float4*)(offsets + (size_t)id * NO + col);
    #pragma unroll
    for (int r = 0; r < TM; r++) {
        lv[r][0] += off4.x; lv[r][1] += off4.y;
        lv[r][2] += off4.z; lv[r][3] += off4.w;
    }

    // Row max (block-wide over 2048 cols)
    #pragma unroll
    for (int r = 0; r < TM; r++) {
        float m = fmaxf(fmaxf(lv[r][0], lv[r][1]), fmaxf(lv[r][2], lv[r][3]));
        m = warpMax(m);
        if ((tid & 31) == 0) wred[r * 16 + wid] = m;
    }
    __syncthreads();
    if (tid < TM) {
        float m = wred[tid * 16];
        #pragma unroll
        for (int w = 1; w < 16; w++) m = fmaxf(m, wred[tid * 16 + w]);
        rowmax_s[tid] = m;
    }
    __syncthreads();

    // Exp + row sum
    #pragma unroll
    for (int r = 0; r < TM; r++) {
        const float rm = rowmax_s[r];
        float e0 = __expf(lv[r][0] - rm);
        float e1 = __expf(lv[r][1] - rm);
        float e2 = __expf(lv[r][2] - rm);
        float e3 = __expf(lv[r][3] - rm);
        lv[r][0] = e0; lv[r][1] = e1; lv[r][2] = e2; lv[r][3] = e3;
        float s = warpSum(e0 + e1 + e2 + e3);
        if ((tid & 31) == 0) wred[r * 16 + wid] = s;
    }
    __syncthreads();
    if (tid < TM) {
        float s = wred[tid * 16];
        #pragma unroll
        for (int w = 1; w < 16; w++) s += wred[tid * 16 + w];
        rowsum_s[tid] = s;
    }
    __syncthreads();

    // Scale and write mu (coalesced float4).
    #pragma unroll
    for (int r = 0; r < TM; r++) {
        int row = rows_s[r];
        if (row >= 0) {
            float sc = sf_s[r] / rowsum_s[r];
            float4 o;
            o.x = lv[r][0] * sc; o.y = lv[r][1] * sc;
            o.z = lv[r][2] * sc; o.w = lv[r][3] * sc;
            *(float4*)(out + (size_t)row * NO + col) = o;
        }
    }
}

// ---------- kernel 3: theta = exp(px_r), appended after mu ----------
__global__ void theta_kernel(const float* __restrict__ px_r, float* __restrict__ out) {
    int i = blockIdx.x * blockDim.x + threadIdx.x;
    if (i < NO) out[(size_t)BN * NO + i] = expf(px_r[i]);
}

extern "C" void kernel_launch(void* const* d_in, const int* in_sizes, int n_in,
                              void* d_out, int out_size) {
    const float* z    = (const float*)d_in[0];
    const float* sf   = (const float*)d_in[1];
    const float* aw   = (const float*)d_in[2];
    const float* as   = (const float*)d_in[3];
    const float* off  = (const float*)d_in[4];
    const float* pxr  = (const float*)d_in[5];
    float* out = (float*)d_out;

    sort_kernel<<<1, 256>>>(z);
    dim3 grid(NU, MAXTILES);
    decoder_kernel<<<grid, NT>>>(z, sf, aw, as, off, out);
    theta_kernel<<<(NO + 255) / 256, 256>>>(pxr, out);
}

// round 3
// speedup vs baseline: 1.3085x; 1.3085x over previous
#include <cuda_runtime.h>
#include <cstdint>

#define BN   2048      // batch rows
#define NL   64        // latent dim
#define NU   16        // nuisance dim
#define NO   2048      // output dim
#define ZS   (NL + NU) // z row stride (80)
#define TM   16        // rows per decoder tile (same nuisance id)
#define NT   512       // decoder threads: thread t owns cols [4t, 4t+4)
#define MAXTILES (BN / TM)   // 128 tiles worst case per id

// Device-global scratch (no allocations allowed).
__device__ float g_Acomb[NU * NL * NO];   // 8 MB: amat_w + amat_site[id]
__device__ int   g_hist[NU];
__device__ int   g_bucket[NU * BN];       // fixed-stride buckets; order within group irrelevant

// ---------- packed f32x2 helpers (Blackwell FFMA2, PTX-only path) ----------
typedef unsigned long long ull;
__device__ __forceinline__ void fma2(ull& d, ull a, ull b) {
    asm("fma.rn.f32x2 %0, %1, %2, %0;" : "+l"(d) : "l"(a), "l"(b));
}
__device__ __forceinline__ void unpack2(ull v, float& x, float& y) {
    asm("mov.b64 {%0, %1}, %2;" : "=f"(x), "=f"(y) : "l"(v));
}
__device__ __forceinline__ float warpMax(float v) {
    #pragma unroll
    for (int o = 16; o > 0; o >>= 1) v = fmaxf(v, __shfl_xor_sync(0xFFFFFFFFu, v, o));
    return v;
}
__device__ __forceinline__ float warpSum(float v) {
    #pragma unroll
    for (int o = 16; o > 0; o >>= 1) v += __shfl_xor_sync(0xFFFFFFFFu, v, o);
    return v;
}

// ---------- kernel 1: Acomb = amat_w + amat_site[id]; also zero hist ----------
// grid covers NU*NL*NO/4 float4s.
__global__ void precombine_kernel(const float* __restrict__ aw,
                                  const float* __restrict__ as) {
    if (blockIdx.x == 0 && threadIdx.x < NU) g_hist[threadIdx.x] = 0;
    int i = blockIdx.x * blockDim.x + threadIdx.x;         // float4 index
    const int per_id = NL * NO / 4;                        // 32768 float4 per id
    float4 s4 = ((const float4*)as)[i];
    float4 w4 = ((const float4*)aw)[i % per_id];
    float4 o;
    o.x = w4.x + s4.x; o.y = w4.y + s4.y;
    o.z = w4.z + s4.z; o.w = w4.w + s4.w;
    ((float4*)g_Acomb)[i] = o;
}

// ---------- kernel 2: per-row argmax id + bucket scatter + theta ----------
// 2048 threads, one per row (and one per theta element).
__global__ void assign_kernel(const float* __restrict__ z,
                              const float* __restrict__ px_r,
                              float* __restrict__ out) {
    int r = blockIdx.x * blockDim.x + threadIdx.x;         // 0..2047
    // theta = exp(px_r)
    out[(size_t)BN * NO + r] = expf(px_r[r]);

    const float4* zn = (const float4*)(z + (size_t)r * ZS + NL);  // 16B aligned
    float4 a = zn[0], b = zn[1], c = zn[2], d = zn[3];
    float v[NU] = {a.x, a.y, a.z, a.w, b.x, b.y, b.z, b.w,
                   c.x, c.y, c.z, c.w, d.x, d.y, d.z, d.w};
    int best = 0; float bv = v[0];
    #pragma unroll
    for (int j = 1; j < NU; j++)
        if (v[j] > bv) { bv = v[j]; best = j; }            // first-max wins (jnp.argmax)
    int pos = atomicAdd(&g_hist[best], 1);
    g_bucket[best * BN + pos] = r;
}

// ---------- kernel 3: grouped fused decoder ----------
// grid = (NU, MAXTILES). Block (id, tile): TM rows of group id; thread t owns
// output cols [4t, 4t+4) as two f32x2 pairs per row.
__global__ __launch_bounds__(NT, 1)
void decoder_kernel(const float* __restrict__ z,
                    const float* __restrict__ size_factor,
                    const float* __restrict__ offsets,
                    float* __restrict__ out) {
    const int id   = blockIdx.x;
    const int tile = blockIdx.y;
    const int cnt  = g_hist[id];
    const int base = tile * TM;
    if (base >= cnt) return;

    __shared__ float2 zdup[NL][TM];   // (v, v) per (l, row) for f32x2 broadcast
    __shared__ float  sf_s[TM];
    __shared__ int    rows_s[TM];
    __shared__ float  wred[TM * 16];
    __shared__ float  rowmax_s[TM];
    __shared__ float  rowsum_s[TM];

    const int tid = threadIdx.x;
    const int wid = tid >> 5;
    const int col = tid * 4;

    if (tid < TM) {
        int row = (base + tid < cnt) ? g_bucket[id * BN + base + tid] : -1;
        rows_s[tid] = row;
        sf_s[tid] = (row >= 0) ? size_factor[row] : 1.0f;
    }
    __syncthreads();

    // Stage z duplicated: zdup[l][r] = (z[row r][l], same)
    for (int i = tid; i < TM * NL; i += NT) {
        int r = i & (TM - 1), l = i >> 4;    // i = l*TM + r
        int row = rows_s[r];
        float v = (row >= 0) ? z[(size_t)row * ZS + l] : 0.0f;
        zdup[l][r] = make_float2(v, v);
    }
    __syncthreads();

    const float* Ac = g_Acomb + (size_t)id * NL * NO + col;

    ull acc[TM][2];
    #pragma unroll
    for (int r = 0; r < TM; r++) { acc[r][0] = 0ull; acc[r][1] = 0ull; }

    #pragma unroll 4
    for (int l = 0; l < NL; l++) {
        ulonglong2 ap = *(const ulonglong2*)(Ac + (size_t)l * NO);  // (c0,c1),(c2,c3)
        const ull* zl = (const ull*)zdup[l];
        #pragma unroll
        for (int r = 0; r < TM; r++) {
            ull zp = zl[r];                  // LDS.64 broadcast
            fma2(acc[r][0], ap.x, zp);
            fma2(acc[r][1], ap.y, zp);
        }
    }

    // Unpack logits + offsets row
    float lv[TM][4];
    const float4 off4 = *(const float4*)(offsets + (size_t)id * NO + col);
    #pragma unroll
    for (int r = 0; r < TM; r++) {
        unpack2(acc[r][0], lv[r][0], lv[r][1]);
        unpack2(acc[r][1], lv[r][2], lv[r][3]);
        lv[r][0] += off4.x; lv[r][1] += off4.y;
        lv[r][2] += off4.z; lv[r][3] += off4.w;
    }

    // Row max (block-wide over 2048 cols)
    #pragma unroll
    for (int r = 0; r < TM; r++) {
        float m = fmaxf(fmaxf(lv[r][0], lv[r][1]), fmaxf(lv[r][2], lv[r][3]));
        m = warpMax(m);
        if ((tid & 31) == 0) wred[r * 16 + wid] = m;
    }
    __syncthreads();
    if (tid < TM) {
        float m = wred[tid * 16];
        #pragma unroll
        for (int w = 1; w < 16; w++) m = fmaxf(m, wred[tid * 16 + w]);
        rowmax_s[tid] = m;
    }
    __syncthreads();

    // Exp + row sum
    #pragma unroll
    for (int r = 0; r < TM; r++) {
        const float rm = rowmax_s[r];
        float e0 = __expf(lv[r][0] - rm);
        float e1 = __expf(lv[r][1] - rm);
        float e2 = __expf(lv[r][2] - rm);
        float e3 = __expf(lv[r][3] - rm);
        lv[r][0] = e0; lv[r][1] = e1; lv[r][2] = e2; lv[r][3] = e3;
        float s = warpSum(e0 + e1 + e2 + e3);
        if ((tid & 31) == 0) wred[r * 16 + wid] = s;
    }
    __syncthreads();
    if (tid < TM) {
        float s = wred[tid * 16];
        #pragma unroll
        for (int w = 1; w < 16; w++) s += wred[tid * 16 + w];
        rowsum_s[tid] = s;
    }
    __syncthreads();

    // Scale and write mu (coalesced float4).
    #pragma unroll
    for (int r = 0; r < TM; r++) {
        int row = rows_s[r];
        if (row >= 0) {
            float sc = sf_s[r] / rowsum_s[r];
            float4 o;
            o.x = lv[r][0] * sc; o.y = lv[r][1] * sc;
            o.z = lv[r][2] * sc; o.w = lv[r][3] * sc;
            *(float4*)(out + (size_t)row * NO + col) = o;
        }
    }
}

extern "C" void kernel_launch(void* const* d_in, const int* in_sizes, int n_in,
                              void* d_out, int out_size) {
    const float* z    = (const float*)d_in[0];
    const float* sf   = (const float*)d_in[1];
    const float* aw   = (const float*)d_in[2];
    const float* as   = (const float*)d_in[3];
    const float* off  = (const float*)d_in[4];
    const float* pxr  = (const float*)d_in[5];
    float* out = (float*)d_out;

    // 524288 float4s / 512 = 1024 blocks
    precombine_kernel<<<(NU * NL * NO / 4) / 512, 512>>>(aw, as);
    assign_kernel<<<BN / 256, 256>>>(z, pxr, out);
    dim3 grid(NU, MAXTILES);
    decoder_kernel<<<grid, NT>>>(z, sf, off, out);
}